// round 6
// baseline (speedup 1.0000x reference)
#include <cuda_runtime.h>
#include <cuda_bf16.h>

// Problem constants
#define B_      1024
#define T_      120
#define E_      50
#define H_      300
#define C_      5
#define G_      1200          // 4*H
#define K_      350           // E + H
#define VOCAB_  50000

// Tiling
#define NBB     8             // b-blocks
#define BR      128           // rows per b-block
#define NSL     15            // h-slices
#define HC      20            // h-cols per slice
#define GC      80            // gate cols per slice (4*HC)
#define NCTA    120           // NBB*NSL, <= 148 SMs -> all co-resident
#define KC      35            // k-chunk
#define NCH     10            // K_/KC
#define THREADS 128           // 4 warps: warp=cg (col group), lanes=rg (row group)

#define SMEM_WS_FLOATS  (K_*GC)        // 28000 floats = 112000 B
#define SMEM_BIAS_OFF   (K_*GC)        // 80 floats
#define SMEM_A_BYTEOFF  ((K_*GC + GC) * 4)   // 112320, 16B aligned
#define SMEM_MAIN       (SMEM_A_BYTEOFF + 2*KC*BR*8)  // +71680 = 184000 B

typedef unsigned long long ull;

// ---------------------------------------------------------------- scratch
__device__ float    g_hs[(size_t)(T_+1) * H_ * B_];   // hs[t][h][b], ~148.7 MB
__device__ float    g_partial_ce[T_];
__device__ float    g_partial_cnt[T_];
__device__ unsigned g_count;

// ---------------------------------------------------------------- helpers
__device__ __forceinline__ void ffma2(ull &d, ull a, ull b) {
    asm("fma.rn.f32x2 %0, %1, %2, %0;" : "+l"(d) : "l"(a), "l"(b));
}
__device__ __forceinline__ ull pack2(float lo, float hi) {
    ull r; asm("mov.b64 %0, {%1, %2};" : "=l"(r) : "f"(lo), "f"(hi)); return r;
}
__device__ __forceinline__ float lo2(ull v) { return __uint_as_float((unsigned)v); }
__device__ __forceinline__ float hi2(ull v) { return __uint_as_float((unsigned)(v >> 32)); }

__device__ __forceinline__ float sigf(float x) {
    return __fdividef(1.0f, 1.0f + __expf(-x));
}
__device__ __forceinline__ float tanh_f(float x) {
    return 2.0f * sigf(2.0f * x) - 1.0f;
}

// ---------------------------------------------------------------- init
__global__ void init_kernel() {
    int idx = blockIdx.x * blockDim.x + threadIdx.x;
    if (idx < H_ * B_) g_hs[idx] = 0.0f;   // hs[0] = h0 = 0
    if (idx == 0) g_count = 0u;
}

// ---------------------------------------------------------------- main LSTM
__global__ void __launch_bounds__(THREADS, 1)
lstm_main(const int* __restrict__ tokens,
          const float* __restrict__ emb,
          const float* __restrict__ Wx,
          const float* __restrict__ Wh,
          const float* __restrict__ bias)
{
    extern __shared__ char smem_raw[];
    float*  Ws     = (float*)smem_raw;                       // [K_][GC]
    float*  bias_s = Ws + SMEM_BIAS_OFF;                     // [GC]
    float2* As2    = (float2*)(smem_raw + SMEM_A_BYTEOFF);   // [2][KC][BR], duplicated {v,v}

    const int tid = threadIdx.x;
    const int cg  = tid >> 5;    // 0..3  (col group: 20 gate cols = 5 hcols)
    const int rg  = tid & 31;    // 0..31 (row group: 4 rows)
    const int bb  = blockIdx.x / NSL;
    const int sl  = blockIdx.x % NSL;
    const int b0  = bb * BR;
    const int h0  = sl * HC;

    // ---- one-time: weights + bias into SMEM (col order: [hcol][gate i,j,f,o])
    for (int idx = tid; idx < K_ * GC; idx += THREADS) {
        int k = idx / GC, c = idx % GC;
        int hcl = c >> 2, g = c & 3;
        int col = g * H_ + h0 + hcl;
        Ws[idx] = (k < E_) ? Wx[k * G_ + col] : Wh[(k - E_) * G_ + col];
    }
    for (int c = tid; c < GC; c += THREADS) {
        int hcl = c >> 2, g = c & 3;
        bias_s[c] = bias[g * H_ + h0 + hcl];
    }
    __syncthreads();

    float cst[4][5];
    #pragma unroll
    for (int r = 0; r < 4; ++r)
        #pragma unroll
        for (int q = 0; q < 5; ++q) cst[r][q] = 0.0f;

    float stage[KC];
    const int bcol = tid;   // this thread stages column b = b0 + bcol

    for (int t = 0; t < T_; ++t) {
        const int    tok    = tokens[(b0 + bcol) * T_ + t];
        const float* embrow = emb + (size_t)tok * E_;
        const float* hprev  = g_hs + (size_t)t * (H_ * B_) + b0 + bcol;  // + h*B_

        // prefetch chunk 0 (k 0..34: all embedding)
        #pragma unroll
        for (int e = 0; e < KC; ++e) stage[e] = embrow[e];

        // accumulators start at bias
        ull acc[4][10];
        #pragma unroll
        for (int p = 0; p < 10; ++p) {
            ull bp = pack2(bias_s[cg * 20 + 2 * p], bias_s[cg * 20 + 2 * p + 1]);
            #pragma unroll
            for (int r = 0; r < 4; ++r) acc[r][p] = bp;
        }

        for (int ch = 0; ch < NCH; ++ch) {
            float2* buf = As2 + (ch & 1) * (KC * BR);
            #pragma unroll
            for (int e = 0; e < KC; ++e)
                buf[e * BR + bcol] = make_float2(stage[e], stage[e]);
            __syncthreads();

            if (ch + 1 < NCH) {
                const int kgb = (ch + 1) * KC;
                #pragma unroll
                for (int e = 0; e < KC; ++e) {
                    int kg = kgb + e;
                    stage[e] = (kg < E_) ? embrow[kg]
                                         : __ldcg(hprev + (size_t)(kg - E_) * B_);
                }
            }

            const float*  wk = Ws + (size_t)ch * KC * GC + cg * 20;
            const float2* ak = buf + rg * 4;
            #pragma unroll 5
            for (int kk = 0; kk < KC; ++kk) {
                ulonglong2 A01 = *(const ulonglong2*)(ak);
                ulonglong2 A23 = *(const ulonglong2*)(ak + 2);
                const ulonglong2* w = (const ulonglong2*)wk;
                ulonglong2 W0 = w[0], W1 = w[1], W2 = w[2], W3 = w[3], W4 = w[4];
                ull aarr[4]  = {A01.x, A01.y, A23.x, A23.y};
                ull warr[10] = {W0.x, W0.y, W1.x, W1.y, W2.x, W2.y, W3.x, W3.y, W4.x, W4.y};
                #pragma unroll
                for (int r = 0; r < 4; ++r)
                    #pragma unroll
                    for (int p = 0; p < 10; ++p)
                        ffma2(acc[r][p], aarr[r], warr[p]);
                ak += BR;
                wk += GC;
            }
        }

        // ---- gates + state update + h write (hs[t+1][h][b])
        const size_t outbase = (size_t)(t + 1) * H_ * B_;
        #pragma unroll
        for (int q = 0; q < 5; ++q) {
            float hn[4];
            #pragma unroll
            for (int r = 0; r < 4; ++r) {
                float zi = lo2(acc[r][2 * q]);
                float zj = hi2(acc[r][2 * q]);
                float zf = lo2(acc[r][2 * q + 1]);
                float zo = hi2(acc[r][2 * q + 1]);
                float ig = sigf(zi);
                float jg = tanh_f(zj);
                float fg = sigf(zf + 1.0f);      // FORGET_BIAS
                float og = sigf(zo);
                float cn = fg * cst[r][q] + ig * jg;
                cst[r][q] = cn;
                hn[r] = og * tanh_f(cn);
            }
            int h = h0 + cg * 5 + q;
            float4* dst = (float4*)(g_hs + outbase + (size_t)h * B_ + b0 + rg * 4);
            *dst = make_float4(hn[0], hn[1], hn[2], hn[3]);
        }

        // ---- grid barrier (all 120 CTAs co-resident; monotonic ticket)
        if (t + 1 < T_) {
            __threadfence();
            __syncthreads();
            if (tid == 0) {
                atomicAdd(&g_count, 1u);
                const unsigned target = (unsigned)(t + 1) * NCTA;
                while (*(volatile unsigned*)&g_count < target) __nanosleep(64);
                __threadfence();
            }
            __syncthreads();
        }
    }
}

// ---------------------------------------------------------------- CE loss
__global__ void __launch_bounds__(256)
ce_kernel(const int* __restrict__ labels, const void* __restrict__ maskp,
          const float* __restrict__ U, const float* __restrict__ b2)
{
    __shared__ float    Us[H_ * C_];
    __shared__ float    b2s[C_];
    __shared__ unsigned flg_s[8];
    __shared__ float    redce[8], redm[8];

    const int t = blockIdx.x;
    const int tid = threadIdx.x;
    const int lane = tid & 31, wid = tid >> 5;

    for (int i = tid; i < H_ * C_; i += 256) Us[i] = U[i];
    if (tid < C_) b2s[tid] = b2[tid];

    // ---- detect mask encoding (int32 0/1, byte 0/1, or float 0.0/1.0)
    const unsigned* mi = (const unsigned*)maskp;
    unsigned fl = 0;
    for (int i = tid; i < (B_ * T_) / 4; i += 256) {       // safe in all layouts
        unsigned v = mi[i];
        if (v & ~1u)                        fl |= 1;       // not int32 {0,1}
        if (v != 0u && v != 0x3F800000u)    fl |= 2;       // not float {0,1.0}
        if (v & 0xFEFEFEFEu)                fl |= 4;       // not bytes {0,1}
    }
    #pragma unroll
    for (int off = 16; off; off >>= 1) fl |= __shfl_down_sync(0xffffffffu, fl, off);
    if (lane == 0) flg_s[wid] = fl;
    __syncthreads();
    if (tid == 0) {
        unsigned a = 0;
        for (int w = 0; w < 8; ++w) a |= flg_s[w];
        flg_s[0] = a;
    }
    __syncthreads();
    fl = flg_s[0];
    const int mode = (!(fl & 1)) ? 0 : ((!(fl & 4)) ? 1 : ((!(fl & 2)) ? 2 : 0));

    float sce = 0.0f, sm = 0.0f;
    for (int b = tid; b < B_; b += 256) {
        float acc[C_];
        #pragma unroll
        for (int c = 0; c < C_; ++c) acc[c] = b2s[c];
        const float* hp = g_hs + (size_t)(t + 1) * H_ * B_ + b;
        #pragma unroll 4
        for (int h = 0; h < H_; ++h) {
            float v = hp[(size_t)h * B_];
            #pragma unroll
            for (int c = 0; c < C_; ++c) acc[c] += v * Us[h * C_ + c];
        }
        float mx = acc[0];
        #pragma unroll
        for (int c = 1; c < C_; ++c) mx = fmaxf(mx, acc[c]);
        float s = 0.0f;
        #pragma unroll
        for (int c = 0; c < C_; ++c) s += __expf(acc[c] - mx);
        float lse = mx + __logf(s);
        int lab = labels[b * T_ + t];
        lab = max(0, min(C_ - 1, lab));
        float ce = lse - acc[lab];

        const int j = b * T_ + t;
        float mk;
        if (mode == 0)      mk = ((const int*)maskp)[j] ? 1.0f : 0.0f;
        else if (mode == 1) mk = ((const unsigned char*)maskp)[j] ? 1.0f : 0.0f;
        else                mk = (((const float*)maskp)[j] != 0.0f) ? 1.0f : 0.0f;

        sce += ce * mk;
        sm  += mk;
    }

    #pragma unroll
    for (int off = 16; off; off >>= 1) {
        sce += __shfl_down_sync(0xffffffffu, sce, off);
        sm  += __shfl_down_sync(0xffffffffu, sm,  off);
    }
    if (lane == 0) { redce[wid] = sce; redm[wid] = sm; }
    __syncthreads();
    if (tid == 0) {
        float a = 0.0f, c = 0.0f;
        for (int w = 0; w < 8; ++w) { a += redce[w]; c += redm[w]; }
        g_partial_ce[t]  = a;
        g_partial_cnt[t] = c;
    }
}

__global__ void fin_kernel(float* out) {
    float a = 0.0f, c = 0.0f;
    for (int t = 0; t < T_; ++t) { a += g_partial_ce[t]; c += g_partial_cnt[t]; }
    out[0] = a / c;
}

// ---------------------------------------------------------------- launch
extern "C" void kernel_launch(void* const* d_in, const int* in_sizes, int n_in,
                              void* d_out, int out_size)
{
    cudaFuncSetAttribute(lstm_main, cudaFuncAttributeMaxDynamicSharedMemorySize, SMEM_MAIN);

    const int*   tokens = (const int*)  d_in[0];
    const int*   labels = (const int*)  d_in[1];
    const void*  mask   =               d_in[2];
    const float* emb    = (const float*)d_in[3];
    const float* Wx     = (const float*)d_in[4];
    const float* Wh     = (const float*)d_in[5];
    const float* b      = (const float*)d_in[6];
    const float* U      = (const float*)d_in[7];
    const float* b2     = (const float*)d_in[8];
    float*       out    = (float*)d_out;

    init_kernel<<<(H_ * B_ + 1023) / 1024, 1024>>>();
    lstm_main<<<NCTA, THREADS, SMEM_MAIN>>>(tokens, emb, Wx, Wh, b);
    ce_kernel<<<T_, 256>>>(labels, mask, U, b2);
    fin_kernel<<<1, 1>>>(out);
}